// round 10
// baseline (speedup 1.0000x reference)
#include <cuda_runtime.h>

// ---------------- problem caps (from setup_inputs) ----------------
#define CH 128          // channel
#define CH4 32          // channel / 4 (float4 per row)
#define MAXN 100000     // max(n_entities, n_users)
#define MAXE 600000     // kg edges
#define MAXI 500000     // inter edges

// ---------------- static device scratch (no allocation allowed) ----
__device__ float g_ent[(size_t)MAXN * CH];   // hop-1 output ping buffer
__device__ int   g_cnt[MAXN];
__device__ int   g_part[512];
__device__ int   g_kg_offs[MAXN + 1];
__device__ int   g_kg_cur[MAXN];
__device__ int   g_kg_ids[MAXE];
__device__ int   g_u_offs[MAXN + 1];
__device__ int   g_u_cur[MAXN];
__device__ int   g_u_ids[MAXI];
__device__ int   g_stride;   // 1 if index tensors are int32, 2 if int64 (LE low word)

// ---------------- index dtype detection ----------------------------
// edge_type values are in [1,16): never zero. If the tensor is int64 on a
// little-endian machine, its int32-word view alternates value,0,value,0,...
// If int32, every word is nonzero. One detection governs all index tensors
// (they share the same materialization path).
__global__ void detect_kernel(const int* __restrict__ type_words) {
    int odd_zero = 1;
#pragma unroll
    for (int i = 0; i < 8; i++)
        if (type_words[2 * i + 1] != 0) odd_zero = 0;
    g_stride = odd_zero ? 2 : 1;
}

// ---------------- CSR build ----------------------------------------
__global__ void count_kernel(const int* __restrict__ idx, int n_edges) {
    int e = blockIdx.x * blockDim.x + threadIdx.x;
    if (e < n_edges) atomicAdd(&g_cnt[idx[(size_t)e * g_stride]], 1);
}

// exclusive scan of cnt[0..n) -> offs[0..n), offs[n]=total.
__global__ void scan_block_sums(const int* __restrict__ cnt, int* __restrict__ part, int n) {
    __shared__ int wsum[8];
    int tid = threadIdx.x, lane = tid & 31, wid = tid >> 5;
    int base = blockIdx.x * 1024 + tid * 4;
    int s = 0;
#pragma unroll
    for (int k = 0; k < 4; k++) { int i = base + k; if (i < n) s += cnt[i]; }
#pragma unroll
    for (int d = 16; d; d >>= 1) s += __shfl_xor_sync(0xffffffffu, s, d);
    if (lane == 0) wsum[wid] = s;
    __syncthreads();
    if (tid == 0) {
        int tot = 0;
#pragma unroll
        for (int w = 0; w < 8; w++) tot += wsum[w];
        part[blockIdx.x] = tot;
    }
}

__global__ void scan_partials(int* __restrict__ part, int nb, int* __restrict__ total_out) {
    __shared__ int sh[256];
    int tid = threadIdx.x;
    int v = (tid < nb) ? part[tid] : 0;
    sh[tid] = v;
    __syncthreads();
    for (int d = 1; d < 256; d <<= 1) {
        int t = (tid >= d) ? sh[tid - d] : 0;
        __syncthreads();
        sh[tid] += t;
        __syncthreads();
    }
    if (tid < nb) part[tid] = sh[tid] - v;     // exclusive block prefix
    if (tid == 255) *total_out = sh[255];      // grand total -> offs[n]
}

__global__ void scan_write(const int* __restrict__ cnt, const int* __restrict__ part,
                           int* __restrict__ offs, int n) {
    __shared__ int wsum[8];
    __shared__ int woff[8];
    int tid = threadIdx.x, lane = tid & 31, wid = tid >> 5;
    int base = blockIdx.x * 1024 + tid * 4;
    int v[4];
    int ts = 0;
#pragma unroll
    for (int k = 0; k < 4; k++) {
        int i = base + k;
        v[k] = (i < n) ? cnt[i] : 0;
        ts += v[k];
    }
    int incl = ts;
#pragma unroll
    for (int d = 1; d < 32; d <<= 1) {
        int t = __shfl_up_sync(0xffffffffu, incl, d);
        if (lane >= d) incl += t;
    }
    if (lane == 31) wsum[wid] = incl;
    __syncthreads();
    if (tid == 0) {
        int r = 0;
#pragma unroll
        for (int i = 0; i < 8; i++) { woff[i] = r; r += wsum[i]; }
    }
    __syncthreads();
    int run = part[blockIdx.x] + woff[wid] + (incl - ts);
#pragma unroll
    for (int k = 0; k < 4; k++) {
        int i = base + k;
        if (i < n) offs[i] = run;
        run += v[k];
    }
}

__global__ void fill_kernel(const int* __restrict__ idx, int n_edges,
                            int* __restrict__ cur, int* __restrict__ ids) {
    int e = blockIdx.x * blockDim.x + threadIdx.x;
    if (e < n_edges) {
        int h = idx[(size_t)e * g_stride];
        int p = atomicAdd(&cur[h], 1);
        ids[p] = e;
    }
}

// deterministic FP accumulation order: sort each segment's edge ids
__global__ void sort_seg(const int* __restrict__ offs, int* __restrict__ ids, int n) {
    int i = blockIdx.x * blockDim.x + threadIdx.x;
    if (i >= n) return;
    int b = offs[i], e = offs[i + 1];
    for (int j = b + 1; j < e; j++) {
        int v = ids[j];
        int k = j - 1;
        while (k >= b && ids[k] > v) { ids[k + 1] = ids[k]; k--; }
        ids[k + 1] = v;
    }
}

// ---------------- hop: fused attention + aggregate + l2norm --------
// One warp per entity. Lane owns 4 channels. Softmax max-shift and
// denominator cancel under the trailing L2 normalization.
// tails are the second row of edge_index: word offset (E + e) * stride.
__global__ __launch_bounds__(256) void hop_kernel(
    const float* __restrict__ ent_in, const float* __restrict__ rel,
    const int* __restrict__ offs, const int* __restrict__ ids,
    const int* __restrict__ eidx, const int* __restrict__ types,
    float* __restrict__ ent_out, int n, int E) {
    int gw = (blockIdx.x * blockDim.x + threadIdx.x) >> 5;
    int lane = threadIdx.x & 31;
    if (gw >= n) return;
    int stride = g_stride;
    int beg = offs[gw], end = offs[gw + 1];
    const float4* in4 = (const float4*)ent_in;
    const float4* rel4 = (const float4*)rel;
    float4 he = in4[(size_t)gw * CH4 + lane];
    float4 acc = make_float4(0.f, 0.f, 0.f, 0.f);
#pragma unroll 2
    for (int i = beg; i < end; i++) {
        int e = ids[i];
        int t = __ldg(&eidx[(size_t)(E + e) * stride]);
        int r = __ldg(&types[(size_t)e * stride]) - 1;
        float4 te = __ldg(&in4[(size_t)t * CH4 + lane]);
        float4 re = __ldg(&rel4[r * CH4 + lane]);
        float p = he.x * re.x * te.x + he.y * re.y * te.y +
                  he.z * re.z * te.z + he.w * re.w * te.w;
#pragma unroll
        for (int d = 16; d; d >>= 1) p += __shfl_xor_sync(0xffffffffu, p, d);
        float w = __expf(__expf(p));   // scores=exp(dot); softmax exp(scores) (shift cancels)
        acc.x += w * te.x; acc.y += w * te.y; acc.z += w * te.z; acc.w += w * te.w;
    }
    float s = acc.x * acc.x + acc.y * acc.y + acc.z * acc.z + acc.w * acc.w;
#pragma unroll
    for (int d = 16; d; d >>= 1) s += __shfl_xor_sync(0xffffffffu, s, d);
    float inv = 1.0f / fmaxf(sqrtf(s), 1e-12f);
    float4 o = make_float4(acc.x * inv, acc.y * inv, acc.z * inv, acc.w * inv);
    ((float4*)ent_out)[(size_t)gw * CH4 + lane] = o;
}

// ---------------- user aggregation + l2norm ------------------------
// items are the second row of inter_edge: word offset (NI + e) * stride.
__global__ __launch_bounds__(256) void user_kernel(
    const float* __restrict__ ent, const int* __restrict__ inter,
    const float* __restrict__ wts, const int* __restrict__ offs,
    const int* __restrict__ ids, float* __restrict__ out, int n, int NI) {
    int gw = (blockIdx.x * blockDim.x + threadIdx.x) >> 5;
    int lane = threadIdx.x & 31;
    if (gw >= n) return;
    int stride = g_stride;
    int beg = offs[gw], end = offs[gw + 1];
    const float4* e4 = (const float4*)ent;
    float4 acc = make_float4(0.f, 0.f, 0.f, 0.f);
#pragma unroll 2
    for (int i = beg; i < end; i++) {
        int e = ids[i];
        int it = __ldg(&inter[(size_t)(NI + e) * stride]);
        float w = __ldg(&wts[e]);
        float4 v = __ldg(&e4[(size_t)it * CH4 + lane]);
        acc.x += w * v.x; acc.y += w * v.y; acc.z += w * v.z; acc.w += w * v.w;
    }
    float s = acc.x * acc.x + acc.y * acc.y + acc.z * acc.z + acc.w * acc.w;
#pragma unroll
    for (int d = 16; d; d >>= 1) s += __shfl_xor_sync(0xffffffffu, s, d);
    float inv = 1.0f / fmaxf(sqrtf(s), 1e-12f);
    float4 o = make_float4(acc.x * inv, acc.y * inv, acc.z * inv, acc.w * inv);
    ((float4*)out)[(size_t)gw * CH4 + lane] = o;
}

// ---------------- launch -------------------------------------------
extern "C" void kernel_launch(void* const* d_in, const int* in_sizes, int n_in,
                              void* d_out, int out_size) {
    const float* item_emb = (const float*)d_in[1];
    const int* edge_index = (const int*)d_in[2];   // int32 OR int64 (runtime-detected)
    const int* edge_type  = (const int*)d_in[3];
    const int* inter_edge = (const int*)d_in[4];
    const float* inter_w  = (const float*)d_in[5];
    const float* rel      = (const float*)d_in[6];

    int n_users = in_sizes[0] / CH;
    int n_ent = in_sizes[1] / CH;
    int E = in_sizes[2] / 2;
    int NI = in_sizes[5];

    void *p_cnt, *p_part, *p_ko, *p_kc, *p_ki, *p_uo, *p_uc, *p_ui, *p_ent;
    cudaGetSymbolAddress(&p_cnt, g_cnt);
    cudaGetSymbolAddress(&p_part, g_part);
    cudaGetSymbolAddress(&p_ko, g_kg_offs);
    cudaGetSymbolAddress(&p_kc, g_kg_cur);
    cudaGetSymbolAddress(&p_ki, g_kg_ids);
    cudaGetSymbolAddress(&p_uo, g_u_offs);
    cudaGetSymbolAddress(&p_uc, g_u_cur);
    cudaGetSymbolAddress(&p_ui, g_u_ids);
    cudaGetSymbolAddress(&p_ent, g_ent);

    // ---- index dtype detection (governs all index tensors) ----
    detect_kernel<<<1, 1>>>(edge_type);

    // ---- KG CSR (by head) ----
    {
        int nb = (n_ent + 1023) / 1024;
        cudaMemsetAsync(p_cnt, 0, (size_t)n_ent * sizeof(int));
        count_kernel<<<(E + 255) / 256, 256>>>(edge_index, E);
        scan_block_sums<<<nb, 256>>>((const int*)p_cnt, (int*)p_part, n_ent);
        scan_partials<<<1, 256>>>((int*)p_part, nb, (int*)p_ko + n_ent);
        scan_write<<<nb, 256>>>((const int*)p_cnt, (const int*)p_part, (int*)p_ko, n_ent);
        cudaMemcpyAsync(p_kc, p_ko, (size_t)n_ent * sizeof(int), cudaMemcpyDeviceToDevice);
        fill_kernel<<<(E + 255) / 256, 256>>>(edge_index, E, (int*)p_kc, (int*)p_ki);
        sort_seg<<<(n_ent + 255) / 256, 256>>>((const int*)p_ko, (int*)p_ki, n_ent);
    }
    // ---- inter CSR (by user) ----
    {
        int nb = (n_users + 1023) / 1024;
        cudaMemsetAsync(p_cnt, 0, (size_t)n_users * sizeof(int));
        count_kernel<<<(NI + 255) / 256, 256>>>(inter_edge, NI);
        scan_block_sums<<<nb, 256>>>((const int*)p_cnt, (int*)p_part, n_users);
        scan_partials<<<1, 256>>>((int*)p_part, nb, (int*)p_uo + n_users);
        scan_write<<<nb, 256>>>((const int*)p_cnt, (const int*)p_part, (int*)p_uo, n_users);
        cudaMemcpyAsync(p_uc, p_uo, (size_t)n_users * sizeof(int), cudaMemcpyDeviceToDevice);
        fill_kernel<<<(NI + 255) / 256, 256>>>(inter_edge, NI, (int*)p_uc, (int*)p_ui);
        sort_seg<<<(n_users + 255) / 256, 256>>>((const int*)p_uo, (int*)p_ui, n_users);
    }

    // ---- 2 hops (n_hops fixed at 2 in this problem) ----
    float* out_user = (float*)d_out;
    float* out_ent = (float*)d_out + (size_t)n_users * CH;
    int hop_blocks = (n_ent * 32 + 255) / 256;
    hop_kernel<<<hop_blocks, 256>>>(item_emb, rel, (const int*)p_ko, (const int*)p_ki,
                                    edge_index, edge_type, (float*)p_ent, n_ent, E);
    hop_kernel<<<hop_blocks, 256>>>((const float*)p_ent, rel, (const int*)p_ko, (const int*)p_ki,
                                    edge_index, edge_type, out_ent, n_ent, E);

    // ---- user aggregation ----
    int user_blocks = (n_users * 32 + 255) / 256;
    user_kernel<<<user_blocks, 256>>>(out_ent, inter_edge, inter_w, (const int*)p_uo,
                                      (const int*)p_ui, out_user, n_users, NI);
}

// round 11
// speedup vs baseline: 1.3051x; 1.3051x over previous
#include <cuda_runtime.h>

// ---------------- problem caps (from setup_inputs) ----------------
#define CH 128          // channel
#define CH4 32          // channel / 4 (float4 per row)
#define MAXN 100000     // max(n_entities, n_users)
#define MAXN2 200000    // n_entities + n_users
#define MAXE 600000     // kg edges
#define MAXI 500000     // inter edges
#define MAXEI 1100000   // combined edge count

// ---------------- static device scratch (no allocation allowed) ----
__device__ float g_ent[(size_t)MAXN * CH];   // hop-1 output ping buffer
__device__ int   g_cnt[MAXN2];               // combined counters (kg | user)
__device__ int   g_part[512];
__device__ int   g_offs[MAXN2 + 2];          // combined CSR offsets
__device__ int   g_cur[MAXN2];
__device__ int   g_ids[MAXEI];               // combined CSR edge ids
__device__ int   g_stride;   // 1 if index tensors are int32, 2 if int64 (LE low word)

// ---------------- index dtype detection ----------------------------
// edge_type values are in [1,16): never zero. If int64 (little-endian), the
// int32-word view alternates value,0,value,0,... One detection governs all
// index tensors (shared materialization path).
__global__ void detect_kernel(const int* __restrict__ type_words) {
    int odd_zero = 1;
#pragma unroll
    for (int i = 0; i < 8; i++)
        if (type_words[2 * i + 1] != 0) odd_zero = 0;
    g_stride = odd_zero ? 2 : 1;
}

// ---------------- combined CSR build -------------------------------
// Thread i < E counts kg edge i by head; thread i in [E, E+NI) counts
// inter edge (i-E) by user (offset n_ent in the combined counter array).
__global__ void count_all(const int* __restrict__ eidx, int E,
                          const int* __restrict__ inter, int NI, int n_ent) {
    int i = blockIdx.x * blockDim.x + threadIdx.x;
    int stride = g_stride;
    if (i < E) {
        atomicAdd(&g_cnt[eidx[(size_t)i * stride]], 1);
    } else if (i < E + NI) {
        atomicAdd(&g_cnt[n_ent + inter[(size_t)(i - E) * stride]], 1);
    }
}

// exclusive scan of g_cnt[0..n) -> g_offs[0..n), g_offs[n]=total.
__global__ void scan_block_sums(const int* __restrict__ cnt, int* __restrict__ part, int n) {
    __shared__ int wsum[8];
    int tid = threadIdx.x, lane = tid & 31, wid = tid >> 5;
    int base = blockIdx.x * 1024 + tid * 4;
    int s = 0;
#pragma unroll
    for (int k = 0; k < 4; k++) { int i = base + k; if (i < n) s += cnt[i]; }
#pragma unroll
    for (int d = 16; d; d >>= 1) s += __shfl_xor_sync(0xffffffffu, s, d);
    if (lane == 0) wsum[wid] = s;
    __syncthreads();
    if (tid == 0) {
        int tot = 0;
#pragma unroll
        for (int w = 0; w < 8; w++) tot += wsum[w];
        part[blockIdx.x] = tot;
    }
}

__global__ void scan_partials(int* __restrict__ part, int nb, int* __restrict__ total_out) {
    __shared__ int sh[256];
    int tid = threadIdx.x;
    int v = (tid < nb) ? part[tid] : 0;
    sh[tid] = v;
    __syncthreads();
    for (int d = 1; d < 256; d <<= 1) {
        int t = (tid >= d) ? sh[tid - d] : 0;
        __syncthreads();
        sh[tid] += t;
        __syncthreads();
    }
    if (tid < nb) part[tid] = sh[tid] - v;     // exclusive block prefix
    if (tid == 255) *total_out = sh[255];      // grand total -> offs[n]
}

__global__ void scan_write(const int* __restrict__ cnt, const int* __restrict__ part,
                           int* __restrict__ offs, int n) {
    __shared__ int wsum[8];
    __shared__ int woff[8];
    int tid = threadIdx.x, lane = tid & 31, wid = tid >> 5;
    int base = blockIdx.x * 1024 + tid * 4;
    int v[4];
    int ts = 0;
#pragma unroll
    for (int k = 0; k < 4; k++) {
        int i = base + k;
        v[k] = (i < n) ? cnt[i] : 0;
        ts += v[k];
    }
    int incl = ts;
#pragma unroll
    for (int d = 1; d < 32; d <<= 1) {
        int t = __shfl_up_sync(0xffffffffu, incl, d);
        if (lane >= d) incl += t;
    }
    if (lane == 31) wsum[wid] = incl;
    __syncthreads();
    if (tid == 0) {
        int r = 0;
#pragma unroll
        for (int i = 0; i < 8; i++) { woff[i] = r; r += wsum[i]; }
    }
    __syncthreads();
    int run = part[blockIdx.x] + woff[wid] + (incl - ts);
#pragma unroll
    for (int k = 0; k < 4; k++) {
        int i = base + k;
        if (i < n) offs[i] = run;
        run += v[k];
    }
}

__global__ void fill_all(const int* __restrict__ eidx, int E,
                         const int* __restrict__ inter, int NI, int n_ent,
                         int* __restrict__ cur, int* __restrict__ ids) {
    int i = blockIdx.x * blockDim.x + threadIdx.x;
    int stride = g_stride;
    if (i < E) {
        int h = eidx[(size_t)i * stride];
        int p = atomicAdd(&cur[h], 1);
        ids[p] = i;
    } else if (i < E + NI) {
        int u = inter[(size_t)(i - E) * stride];
        int p = atomicAdd(&cur[n_ent + u], 1);
        ids[p] = i - E;
    }
}

// deterministic FP accumulation order: sort each segment's edge ids
__global__ void sort_seg(const int* __restrict__ offs, int* __restrict__ ids, int n) {
    int i = blockIdx.x * blockDim.x + threadIdx.x;
    if (i >= n) return;
    int b = offs[i], e = offs[i + 1];
    for (int j = b + 1; j < e; j++) {
        int v = ids[j];
        int k = j - 1;
        while (k >= b && ids[k] > v) { ids[k + 1] = ids[k]; k--; }
        ids[k + 1] = v;
    }
}

// ---------------- hop: fused attention + aggregate + l2norm --------
// One warp per entity; lane owns 4 channels. Softmax max-shift and
// denominator cancel under the trailing L2 normalization.
// Batch strategy: lanes cooperatively load up to 32 edges' (tail, type),
// then iterate via shfl broadcast — one index-fetch latency per 32 edges.
__global__ __launch_bounds__(256) void hop_kernel(
    const float* __restrict__ ent_in, const float* __restrict__ rel,
    const int* __restrict__ offs, const int* __restrict__ ids,
    const int* __restrict__ eidx, const int* __restrict__ types,
    float* __restrict__ ent_out, int n, int E) {
    int gw = (blockIdx.x * blockDim.x + threadIdx.x) >> 5;
    int lane = threadIdx.x & 31;
    if (gw >= n) return;
    int stride = g_stride;
    int beg = offs[gw], end = offs[gw + 1];
    const float4* in4 = (const float4*)ent_in;
    const float4* rel4 = (const float4*)rel;
    float4 he = in4[(size_t)gw * CH4 + lane];
    float4 acc = make_float4(0.f, 0.f, 0.f, 0.f);
    for (int base = beg; base < end; base += 32) {
        int i = base + lane;
        int t = 0, r = 0;
        if (i < end) {
            int e = __ldg(&ids[i]);
            t = __ldg(&eidx[(size_t)(E + e) * stride]);
            r = __ldg(&types[(size_t)e * stride]) - 1;
        }
        int m = end - base; if (m > 32) m = 32;
        for (int k = 0; k < m; k++) {
            int tk = __shfl_sync(0xffffffffu, t, k);
            int rk = __shfl_sync(0xffffffffu, r, k);
            float4 te = __ldg(&in4[(size_t)tk * CH4 + lane]);
            float4 re = __ldg(&rel4[rk * CH4 + lane]);
            float p = he.x * re.x * te.x + he.y * re.y * te.y +
                      he.z * re.z * te.z + he.w * re.w * te.w;
#pragma unroll
            for (int d = 16; d; d >>= 1) p += __shfl_xor_sync(0xffffffffu, p, d);
            float w = __expf(__expf(p));   // exp(scores); shift+denominator cancel
            acc.x += w * te.x; acc.y += w * te.y; acc.z += w * te.z; acc.w += w * te.w;
        }
    }
    float s = acc.x * acc.x + acc.y * acc.y + acc.z * acc.z + acc.w * acc.w;
#pragma unroll
    for (int d = 16; d; d >>= 1) s += __shfl_xor_sync(0xffffffffu, s, d);
    float inv = 1.0f / fmaxf(sqrtf(s), 1e-12f);
    float4 o = make_float4(acc.x * inv, acc.y * inv, acc.z * inv, acc.w * inv);
    ((float4*)ent_out)[(size_t)gw * CH4 + lane] = o;
}

// ---------------- user aggregation + l2norm ------------------------
__global__ __launch_bounds__(256) void user_kernel(
    const float* __restrict__ ent, const int* __restrict__ inter,
    const float* __restrict__ wts, const int* __restrict__ offs,
    const int* __restrict__ ids, float* __restrict__ out, int n, int NI) {
    int gw = (blockIdx.x * blockDim.x + threadIdx.x) >> 5;
    int lane = threadIdx.x & 31;
    if (gw >= n) return;
    int stride = g_stride;
    int beg = offs[gw], end = offs[gw + 1];
    const float4* e4 = (const float4*)ent;
    float4 acc = make_float4(0.f, 0.f, 0.f, 0.f);
    for (int base = beg; base < end; base += 32) {
        int i = base + lane;
        int t = 0; float wt = 0.f;
        if (i < end) {
            int e = __ldg(&ids[i]);
            t = __ldg(&inter[(size_t)(NI + e) * stride]);
            wt = __ldg(&wts[e]);
        }
        int m = end - base; if (m > 32) m = 32;
        for (int k = 0; k < m; k++) {
            int tk = __shfl_sync(0xffffffffu, t, k);
            float wk = __shfl_sync(0xffffffffu, wt, k);
            float4 v = __ldg(&e4[(size_t)tk * CH4 + lane]);
            acc.x += wk * v.x; acc.y += wk * v.y; acc.z += wk * v.z; acc.w += wk * v.w;
        }
    }
    float s = acc.x * acc.x + acc.y * acc.y + acc.z * acc.z + acc.w * acc.w;
#pragma unroll
    for (int d = 16; d; d >>= 1) s += __shfl_xor_sync(0xffffffffu, s, d);
    float inv = 1.0f / fmaxf(sqrtf(s), 1e-12f);
    float4 o = make_float4(acc.x * inv, acc.y * inv, acc.z * inv, acc.w * inv);
    ((float4*)out)[(size_t)gw * CH4 + lane] = o;
}

// ---------------- launch -------------------------------------------
extern "C" void kernel_launch(void* const* d_in, const int* in_sizes, int n_in,
                              void* d_out, int out_size) {
    const float* item_emb = (const float*)d_in[1];
    const int* edge_index = (const int*)d_in[2];   // int32 OR int64 (runtime-detected)
    const int* edge_type  = (const int*)d_in[3];
    const int* inter_edge = (const int*)d_in[4];
    const float* inter_w  = (const float*)d_in[5];
    const float* rel      = (const float*)d_in[6];

    int n_users = in_sizes[0] / CH;
    int n_ent = in_sizes[1] / CH;
    int E = in_sizes[2] / 2;
    int NI = in_sizes[5];
    int n2 = n_ent + n_users;

    void *p_cnt, *p_part, *p_offs, *p_cur, *p_ids, *p_ent;
    cudaGetSymbolAddress(&p_cnt, g_cnt);
    cudaGetSymbolAddress(&p_part, g_part);
    cudaGetSymbolAddress(&p_offs, g_offs);
    cudaGetSymbolAddress(&p_cur, g_cur);
    cudaGetSymbolAddress(&p_ids, g_ids);
    cudaGetSymbolAddress(&p_ent, g_ent);

    // ---- index dtype detection (governs all index tensors) ----
    detect_kernel<<<1, 1>>>(edge_type);

    // ---- combined CSR build (kg by head | inter by user) ----
    {
        int nb = (n2 + 1023) / 1024;
        int ne = E + NI;
        cudaMemsetAsync(p_cnt, 0, (size_t)n2 * sizeof(int));
        count_all<<<(ne + 255) / 256, 256>>>(edge_index, E, inter_edge, NI, n_ent);
        scan_block_sums<<<nb, 256>>>((const int*)p_cnt, (int*)p_part, n2);
        scan_partials<<<1, 256>>>((int*)p_part, nb, (int*)p_offs + n2);
        scan_write<<<nb, 256>>>((const int*)p_cnt, (const int*)p_part, (int*)p_offs, n2);
        cudaMemcpyAsync(p_cur, p_offs, (size_t)n2 * sizeof(int), cudaMemcpyDeviceToDevice);
        fill_all<<<(ne + 255) / 256, 256>>>(edge_index, E, inter_edge, NI, n_ent,
                                            (int*)p_cur, (int*)p_ids);
        sort_seg<<<(n2 + 255) / 256, 256>>>((const int*)p_offs, (int*)p_ids, n2);
    }

    // ---- 2 hops (n_hops fixed at 2 in this problem) ----
    float* out_user = (float*)d_out;
    float* out_ent = (float*)d_out + (size_t)n_users * CH;
    int hop_blocks = (n_ent * 32 + 255) / 256;
    hop_kernel<<<hop_blocks, 256>>>(item_emb, rel, (const int*)p_offs, (const int*)p_ids,
                                    edge_index, edge_type, (float*)p_ent, n_ent, E);
    hop_kernel<<<hop_blocks, 256>>>((const float*)p_ent, rel, (const int*)p_offs, (const int*)p_ids,
                                    edge_index, edge_type, out_ent, n_ent, E);

    // ---- user aggregation (offsets start at combined index n_ent) ----
    int user_blocks = (n_users * 32 + 255) / 256;
    user_kernel<<<user_blocks, 256>>>(out_ent, inter_edge, inter_w,
                                      (const int*)p_offs + n_ent, (const int*)p_ids,
                                      out_user, n_users, NI);
}